// round 16
// baseline (speedup 1.0000x reference)
#include <cuda_runtime.h>
#include <cstdint>

// ---------------------------------------------------------------------------
// SSDBoxHead post-processing.
// Inputs: cls_logits [32,24564,81] f32, bbox_pred [32,24564,4] f32, priors [24564,4] f32
// Output (float32): det_bx [32,100,4] | det_sc [32,100] | det_lb [32,100]
// ---------------------------------------------------------------------------

#define BB    32
#define NN    24564
#define CC    81
#define FG    80
#define KPRE  200
#define KDET  100
#define NTH   256
#define NBIN  2048
#define BUFCAP 1024
#define SPECBITS 0x3D800000u   // 0.0625f : candidate-list threshold
#define NPAIRS (KPRE * (KPRE + 1) / 2)   // 20100

typedef unsigned long long ull;

__device__ float  g_scoresT[(size_t)BB * FG * NN];   // thresholded fg scores [B][80][N]
__device__ float4 g_boxes4[(size_t)BB * NN];         // decoded boxes
__device__ float  g_cls_sc[(size_t)BB * FG * KPRE];  // per-class NMS'd scores
__device__ float4 g_cls_bx4[(size_t)BB * FG * KPRE]; // per-class top-200 boxes
__device__ ull      g_cand[(size_t)BB * FG * BUFCAP]; // per-(b,c) candidate keys (21 MB)
__device__ unsigned g_cnt[BB * FG];                   // per-(b,c) candidate counts

__device__ __forceinline__ ull make_key(unsigned bits, unsigned i)
{
    return ((ull)bits << 32) | (ull)(~i);
}

// ---------------------------------------------------------------------------
// Kernel 0: zero the candidate counters (required per graph replay).
// ---------------------------------------------------------------------------
__global__ void __launch_bounds__(1024) k_zero()
{
    int i = blockIdx.x * 1024 + threadIdx.x;
    if (i < BB * FG) g_cnt[i] = 0u;
}

// ---------------------------------------------------------------------------
// Kernel 1: warp-per-anchor softmax in XLA-GPU reduction order (bit-exact),
// threshold (division skipped when provably below threshold — stored values
// bit-identical), transpose-store; candidate-list append; box decode.
// ---------------------------------------------------------------------------
__global__ void __launch_bounds__(1024) k_prep(const float* __restrict__ logits,
                                               const float* __restrict__ bbox,
                                               const float* __restrict__ priors)
{
    __shared__ float    tile[FG * 33];
    __shared__ unsigned basev[32];

    int tid  = threadIdx.x;
    int w    = tid >> 5;
    int lane = tid & 31;

    int a = blockIdx.x * 32 + w;
    int b = a / NN;
    int n = a - b * NN;

    const float* row = logits + (size_t)a * CC;

    float x0 = row[lane];
    float x1 = row[lane + 32];
    bool  h2 = (lane + 64) < CC;
    float x2 = h2 ? row[lane + 64] : -__int_as_float(0x7f800000);
    float m = fmaxf(fmaxf(x0, x1), x2);
#pragma unroll
    for (int off = 16; off > 0; off >>= 1)
        m = fmaxf(m, __shfl_xor_sync(0xFFFFFFFFu, m, off));

    float e0 = expf(__fsub_rn(x0, m));
    float e1 = expf(__fsub_rn(x1, m));
    float e2 = h2 ? expf(__fsub_rn(x2, m)) : 0.f;

    float acc = __fadd_rn(__fadd_rn(e0, e1), h2 ? e2 : 0.f);
    if (!h2) acc = __fadd_rn(e0, e1);
#pragma unroll
    for (int off = 16; off > 0; off >>= 1)
        acc = __fadd_rn(acc, __shfl_down_sync(0xFFFFFFFFu, acc, off));
    float s = __shfl_sync(0xFFFFFFFFu, acc, 0);

    // e <= skip_thr  ==>  e/s < 0.01 under ANY IEEE rounding (1% margin vs
    // 2^-24 div error) ==> stored value is exactly 0; division skipped.
    float skip_thr = __fmul_rn(s, 0.0099f);
    int   bbase    = b * FG;

#define EMIT_CLASS(EV, CIDX)                                                  \
    {                                                                         \
        float v = 0.f;                                                        \
        if ((EV) > skip_thr) {                                                \
            float q = __fdiv_rn((EV), s);                                     \
            if (q > 0.01f) v = q;                                             \
        }                                                                     \
        tile[(CIDX) * 33 + w] = v;                                            \
        unsigned bits = __float_as_uint(v);                                   \
        if (bits >= SPECBITS) {                                               \
            unsigned p = atomicAdd(&g_cnt[bbase + (CIDX)], 1u);               \
            if (p < BUFCAP)                                                   \
                g_cand[(size_t)(bbase + (CIDX)) * BUFCAP + p] =               \
                    make_key(bits, (unsigned)n);                              \
        }                                                                     \
    }

    if (lane >= 1) EMIT_CLASS(e0, lane - 1);
    EMIT_CLASS(e1, lane + 31);
    if (h2)        EMIT_CLASS(e2, lane + 63);
#undef EMIT_CLASS

    if (lane == 0) {
        basev[w] = (unsigned)(b * FG * NN + n);
        float4 p = ((const float4*)priors)[n];
        float4 t = ((const float4*)bbox)[a];
        float cx = __fadd_rn(__fmul_rn(__fmul_rn(t.x, 0.1f), p.z), p.x);
        float cy = __fadd_rn(__fmul_rn(__fmul_rn(t.y, 0.1f), p.w), p.y);
        float wd = __fmul_rn(expf(__fmul_rn(t.z, 0.2f)), p.z);
        float ht = __fmul_rn(expf(__fmul_rn(t.w, 0.2f)), p.w);
        float hw = __fmul_rn(wd, 0.5f);
        float hh = __fmul_rn(ht, 0.5f);
        float4 bx;
        bx.x = __fsub_rn(cx, hw);
        bx.y = __fsub_rn(cy, hh);
        bx.z = __fadd_rn(cx, hw);
        bx.w = __fadd_rn(cy, hh);
        g_boxes4[a] = bx;
    }
    __syncthreads();

#pragma unroll
    for (int i = tid; i < FG * 32; i += 1024) {
        int c = i >> 5;
        int j = i & 31;
        g_scoresT[(size_t)basev[j] + (size_t)c * NN] = tile[c * 33 + j];
    }
}

// ---------------------------------------------------------------------------
// Selection machinery (validated R7). Key ordering == jax.lax.top_k stable.
// ---------------------------------------------------------------------------
struct Sel {
    union {
        unsigned hist[NBIN];     // 8 KB (fallback path only)
        ull      keys[BUFCAP];   // 8 KB
    } u;
    unsigned chunk[NTH];
    unsigned vals[4];     // [0]=found [1]=bin [2]=above [3]=total
    unsigned counter;
};

// Warp-aggregated histogram add (all 32 lanes must execute; zero bits -> skip).
__device__ __forceinline__ void hist_add(unsigned* hist, unsigned bits, int lane,
                                         int shift)
{
    unsigned bin = bits ? (bits >> shift) : 0xFFFFFFFFu;
    unsigned peers = __match_any_sync(0xFFFFFFFFu, bin);
    int leader = __ffs(peers) - 1;
    if (lane == leader && bits) atomicAdd(&hist[bin], (unsigned)__popc(peers));
}

// Highest-first scan of hist[NBIN]: find bin where cumulative count (from top
// bin downward) first reaches K. Warp-parallel. Requires blockDim == NTH.
__device__ void find_cut(Sel* s, unsigned K)
{
    int tid = threadIdx.x;
    const int CPT = NBIN / NTH;               // 8 bins/thread
    unsigned cs = 0;
    int base = tid * CPT;
#pragma unroll
    for (int j = 0; j < CPT; j++) cs += s->u.hist[base + j];
    s->chunk[tid] = cs;
    __syncthreads();
    if (tid < 32) {
        unsigned ss = 0;
#pragma unroll
        for (int j = 0; j < 8; j++) ss += s->chunk[tid * 8 + j];
        unsigned incl = ss;                    // inclusive suffix sum (lane..31)
#pragma unroll
        for (int off = 1; off < 32; off <<= 1) {
            unsigned t = __shfl_down_sync(0xFFFFFFFFu, incl, off);
            if (tid + off < 32) incl += t;
        }
        unsigned total = __shfl_sync(0xFFFFFFFFu, incl, 0);
        unsigned above = incl - ss;            // strictly-higher lanes
        bool cross = (total >= K) && (above < K) && (incl >= K);
        if (tid == 0) { s->vals[0] = (total >= K) ? 1u : 0u; s->vals[3] = total; }
        if (cross) {
            unsigned acc = above; int bin = -1;
            for (int c = tid * 8 + 7; c >= tid * 8; c--) {
                unsigned cv = s->chunk[c];
                if (acc + cv >= K) {
                    for (int bq = c * CPT + CPT - 1; bq >= c * CPT; bq--) {
                        unsigned hv = s->u.hist[bq];
                        if (acc + hv >= K) { bin = bq; break; }
                        acc += hv;
                    }
                    break;
                }
                acc += cv;
            }
            s->vals[1] = (unsigned)bin;
            s->vals[2] = acc;
        }
    }
    __syncthreads();
}

__device__ void bitonic_desc(ull* keys, int L)
{
    for (int k = 2; k <= L; k <<= 1) {
        for (int j = k >> 1; j > 0; j >>= 1) {
            for (int i = threadIdx.x; i < L; i += NTH) {
                int ixj = i ^ j;
                if (ixj > i) {
                    ull a = keys[i], bkey = keys[ixj];
                    bool up = ((i & k) == 0);
                    if (up ? (a < bkey) : (a > bkey)) {
                        keys[i] = bkey; keys[ixj] = a;
                    }
                }
            }
            __syncthreads();
        }
    }
}

// Sort gathered keys (cnt entries) and emit top-K descending into outK.
__device__ void sort_emit(Sel* s, unsigned cnt, int K, ull* outK)
{
    int tid = threadIdx.x;
    if (cnt > BUFCAP) cnt = BUFCAP;
    int L = 1; while (L < (int)cnt) L <<= 1; if (L < 2) L = 2;
    for (int p = (int)cnt + tid; p < L; p += NTH) s->u.keys[p] = 0ull;
    __syncthreads();
    bitonic_desc(s->u.keys, L);
    for (int j = tid; j < K; j += NTH) outK[j] = s->u.keys[j];
    __syncthreads();
}

// Deficit path (fewer than K positives): gather all, sort, fill stable zeros.
__device__ void deficit_path(const float4* __restrict__ row4, int n, int K,
                             unsigned total, Sel* s, ull* outK)
{
    int tid = threadIdx.x;
    int n4 = n >> 2;
    if (tid == 0) s->counter = 0;
    __syncthreads();
    for (int i = tid; i < n4; i += NTH) {
        float4 v = row4[i];
        unsigned bb[4] = { __float_as_uint(v.x), __float_as_uint(v.y),
                           __float_as_uint(v.z), __float_as_uint(v.w) };
#pragma unroll
        for (int c = 0; c < 4; c++)
            if (bb[c]) {
                unsigned p = atomicAdd(&s->counter, 1u);
                if (p < BUFCAP) s->u.keys[p] = make_key(bb[c], (unsigned)(i * 4 + c));
            }
    }
    __syncthreads();
    int L = 1; while (L < (int)total) L <<= 1; if (L < 2) L = 2;
    for (int p = (int)total + tid; p < L; p += NTH) s->u.keys[p] = 0ull;
    __syncthreads();
    bitonic_desc(s->u.keys, L);
    for (int j = tid; j < (int)total && j < K; j += NTH) outK[j] = s->u.keys[j];
    __syncthreads();
    if (tid == 0) {
        const float* rowf = (const float*)row4;
        int filled = (int)total;
        for (int i = 0; filled < K && i < n; i++)
            if (__float_as_uint(rowf[i]) == 0u)
                outK[filled++] = make_key(0u, (unsigned)i);
    }
    __syncthreads();
}

// Full in-block stable top-K (fallback + k_final; validated R7 path).
__device__ void stable_topk(const float4* __restrict__ row4, int n, int K,
                            Sel* s, ull* outK)
{
    int tid = threadIdx.x;
    int lane = tid & 31;
    int n4 = n >> 2;
    int iters = (n4 + NTH - 1) / NTH;

    for (int i = tid; i < NBIN; i += NTH) s->u.hist[i] = 0;
    __syncthreads();

    for (int it = 0; it < iters; it++) {
        int i = it * NTH + tid;
        bool in = (i < n4);
        float4 v = in ? row4[i] : make_float4(0.f, 0.f, 0.f, 0.f);
        hist_add(s->u.hist, __float_as_uint(v.x), lane, 19);
        hist_add(s->u.hist, __float_as_uint(v.y), lane, 19);
        hist_add(s->u.hist, __float_as_uint(v.z), lane, 19);
        hist_add(s->u.hist, __float_as_uint(v.w), lane, 19);
    }
    __syncthreads();
    find_cut(s, (unsigned)K);

    if (s->vals[0]) {
        unsigned bin   = s->vals[1];
        unsigned above = s->vals[2];
        unsigned inbin = s->u.hist[bin];
        unsigned pivot = bin << 19;
        __syncthreads();    // all hist reads done before keys (union) is written

        if (above + inbin > BUFCAP) {
            for (int i = tid; i < NBIN; i += NTH) s->u.hist[i] = 0;
            __syncthreads();
            for (int it = 0; it < iters; it++) {
                int i = it * NTH + tid;
                bool in = (i < n4);
                float4 v = in ? row4[i] : make_float4(0.f, 0.f, 0.f, 0.f);
                unsigned bb[4] = { __float_as_uint(v.x), __float_as_uint(v.y),
                                   __float_as_uint(v.z), __float_as_uint(v.w) };
#pragma unroll
                for (int c = 0; c < 4; c++) {
                    bool sel = bb[c] && ((bb[c] >> 19) == bin);
                    if (sel) atomicAdd(&s->u.hist[(bb[c] >> 8) & 0x7FFu], 1u);
                }
            }
            __syncthreads();
            find_cut(s, (unsigned)K - above);
            pivot = (bin << 19) | (s->vals[1] << 8);
            __syncthreads();
        }

        if (tid == 0) s->counter = 0;
        __syncthreads();
        for (int i = tid; i < n4; i += NTH) {
            float4 v = row4[i];
            unsigned bb[4] = { __float_as_uint(v.x), __float_as_uint(v.y),
                               __float_as_uint(v.z), __float_as_uint(v.w) };
#pragma unroll
            for (int c = 0; c < 4; c++) {
                if (bb[c] && bb[c] >= pivot) {
                    unsigned p = atomicAdd(&s->counter, 1u);
                    if (p < BUFCAP) s->u.keys[p] = make_key(bb[c], (unsigned)(i * 4 + c));
                }
            }
        }
        __syncthreads();
        sort_emit(s, s->counter, K, outK);
    } else {
        unsigned total = s->vals[3];
        __syncthreads();
        deficit_path(row4, n, K, total, s, outK);
    }
}

// ---------------------------------------------------------------------------
// Kernel 2: per-(batch,class) top-200 from producer-side candidate list
// (fallback: full stable_topk over the row), then bitmap greedy NMS.
// ---------------------------------------------------------------------------
#define NW 7   // ceil(KPRE/32)

struct K2Smem {
    Sel      sel;
    ull      outK[KPRE];
    float4   bxs[KPRE];
    float    scs[KPRE];
    float    area[KPRE];
    unsigned iou_w[KPRE][NW];
    unsigned keepw[NW];
};

__global__ void __launch_bounds__(NTH, 8) k_nms()
{
    __shared__ K2Smem s;
    int bc = blockIdx.x;            // b*80 + c
    int b  = bc / FG;
    int j  = threadIdx.x;

    const float4* row4 = (const float4*)(g_scoresT + (size_t)bc * NN);

    // ---- Fast path: candidate list produced by k_prep.
    // Valid iff KPRE <= cnt <= BUFCAP: every top-KPRE key has bits >= SPECBITS
    // and all such keys were captured (no drops occur unless cnt > BUFCAP).
    // Append order is nondeterministic but the SET is deterministic and the
    // bitonic sort canonicalizes the order.
    unsigned cnt = g_cnt[bc];
    if (cnt >= (unsigned)KPRE && cnt <= BUFCAP) {
        const ull* src = g_cand + (size_t)bc * BUFCAP;
        for (int i = j; i < (int)cnt; i += NTH) s.sel.u.keys[i] = src[i];
        __syncthreads();
        sort_emit(&s.sel, cnt, KPRE, s.outK);
    } else {
        stable_topk(row4, NN, KPRE, &s.sel, s.outK);   // exact fallback (rare)
    }

    if (j < KPRE) {
        ull key = s.outK[j];
        unsigned bits = (unsigned)(key >> 32);
        unsigned idx  = ~(unsigned)(key & 0xFFFFFFFFull);
        float4 bx = g_boxes4[(size_t)b * NN + idx];
        s.scs[j]  = __uint_as_float(bits);
        s.bxs[j]  = bx;
        s.area[j] = __fmul_rn(fmaxf(__fsub_rn(bx.z, bx.x), 0.f),
                              fmaxf(__fsub_rn(bx.w, bx.y), 0.f));
    }
    for (int t = j; t < KPRE * NW; t += NTH) s.iou_w[0][t] = 0u;
    __syncthreads();

    // ---- Triangle IoU (i<=j) with mirror atomicOr into bitmap ----
    for (int t = j; t < NPAIRS; t += NTH) {
        int i = (int)(200.5f - 0.5f * sqrtf(160801.0f - 8.0f * (float)t));
        if (i > KPRE - 1) i = KPRE - 1;
        if (i < 0) i = 0;
        while ((i + 1) * (2 * KPRE - 1 - i + 1) / 2 <= t) i++;
        while (i * (2 * KPRE + 1 - i) / 2 > t) i--;
        int jj = i + (t - i * (2 * KPRE + 1 - i) / 2);

        float4 a = s.bxs[i], bx = s.bxs[jj];
        float lx = fmaxf(a.x, bx.x), ly = fmaxf(a.y, bx.y);
        float rx = fminf(a.z, bx.z), ry = fminf(a.w, bx.w);
        float iw = fmaxf(__fsub_rn(rx, lx), 0.f), ih = fmaxf(__fsub_rn(ry, ly), 0.f);
        float inter = __fmul_rn(iw, ih);
        float uni = __fsub_rn(__fadd_rn(s.area[i], s.area[jj]), inter);
        float iou = __fdiv_rn(inter, fmaxf(uni, 1e-9f));
        if (iou > 0.45f) {
            atomicOr(&s.iou_w[i][jj >> 5], 1u << (jj & 31));
            if (i != jj) atomicOr(&s.iou_w[jj][i >> 5], 1u << (i & 31));
        }
    }
    __syncthreads();

    // ---- Greedy scan (reference lax.scan semantics), single thread ----
    if (j == 0) {
        unsigned sp0 = 0, sp1 = 0, sp2 = 0, sp3 = 0, sp4 = 0, sp5 = 0, sp6 = 0;
#define NMS_WORD(W, SUPPW)                                              \
        {                                                               \
            int lim = KPRE - (W) * 32; if (lim > 32) lim = 32;          \
            unsigned kw = 0;                                            \
            for (int bi = 0; bi < lim; bi++) {                          \
                int i = (W) * 32 + bi;                                  \
                unsigned r0 = s.iou_w[i][0], r1 = s.iou_w[i][1],        \
                         r2 = s.iou_w[i][2], r3 = s.iou_w[i][3],        \
                         r4 = s.iou_w[i][4], r5 = s.iou_w[i][5],        \
                         r6 = s.iou_w[i][6];                            \
                bool ki = (s.scs[i] > 0.f) && !((SUPPW >> bi) & 1u);    \
                if (ki) {                                               \
                    kw |= 1u << bi;                                     \
                    sp0 |= r0; sp1 |= r1; sp2 |= r2; sp3 |= r3;         \
                    sp4 |= r4; sp5 |= r5; sp6 |= r6;                    \
                }                                                       \
            }                                                           \
            s.keepw[W] = kw;                                            \
        }
        NMS_WORD(0, sp0) NMS_WORD(1, sp1) NMS_WORD(2, sp2) NMS_WORD(3, sp3)
        NMS_WORD(4, sp4) NMS_WORD(5, sp5) NMS_WORD(6, sp6)
#undef NMS_WORD
    }
    __syncthreads();

    if (j < KPRE) {
        bool kept = (s.keepw[j >> 5] >> (j & 31)) & 1u;
        size_t o = (size_t)bc * KPRE + j;
        g_cls_sc[o]  = kept ? s.scs[j] : 0.0f;
        g_cls_bx4[o] = s.bxs[j];
    }
}

// ---------------------------------------------------------------------------
// Kernel 3: per-batch stable top-100 over 16000 class-scores; write outputs.
// ---------------------------------------------------------------------------
struct K3Smem {
    Sel sel;
    ull outK[KDET];
};

__global__ void __launch_bounds__(NTH) k_final(float* __restrict__ out)
{
    __shared__ K3Smem s;
    int b = blockIdx.x;
    int j = threadIdx.x;
    const int FLAT = FG * KPRE;     // 16000

    const float4* row4 = (const float4*)(g_cls_sc + (size_t)b * FLAT);
    stable_topk(row4, FLAT, KDET, &s.sel, s.outK);

    if (j < KDET) {
        ull key = s.outK[j];
        unsigned bits = (unsigned)(key >> 32);
        unsigned f    = ~(unsigned)(key & 0xFFFFFFFFull);
        float4 bx = g_cls_bx4[(size_t)b * FLAT + f];
        float* obx = out + ((size_t)b * KDET + j) * 4;
        obx[0] = bx.x; obx[1] = bx.y; obx[2] = bx.z; obx[3] = bx.w;
        out[BB * KDET * 4 + b * KDET + j]             = __uint_as_float(bits);
        out[BB * KDET * 4 + BB * KDET + b * KDET + j] = (float)(f / KPRE + 1);
    }
}

// ---------------------------------------------------------------------------
extern "C" void kernel_launch(void* const* d_in, const int* in_sizes, int n_in,
                              void* d_out, int out_size)
{
    const float* logits = (const float*)d_in[0];
    const float* bbox   = (const float*)d_in[1];
    const float* priors = (const float*)d_in[2];
    float* out = (float*)d_out;

    k_zero<<<(BB * FG + 1023) / 1024, 1024>>>();
    k_prep<<<(BB * NN) / 32, 1024>>>(logits, bbox, priors);
    k_nms<<<BB * FG, NTH>>>();
    k_final<<<BB, NTH>>>(out);
}

// round 17
// speedup vs baseline: 1.3169x; 1.3169x over previous
#include <cuda_runtime.h>
#include <cstdint>

// ---------------------------------------------------------------------------
// SSDBoxHead post-processing.
// Inputs: cls_logits [32,24564,81] f32, bbox_pred [32,24564,4] f32, priors [24564,4] f32
// Output (float32): det_bx [32,100,4] | det_sc [32,100] | det_lb [32,100]
// ---------------------------------------------------------------------------

#define BB    32
#define NN    24564
#define CC    81
#define FG    80
#define KPRE  200
#define KDET  100
#define NTH   256
#define NBIN  2048
#define BUFCAP 1024
#define BMW   768              // bitmap words per (b,c) row: ceil(24564/32)
#define NPAIRS (KPRE * (KPRE + 1) / 2)   // 20100

typedef unsigned long long ull;

__device__ float  g_scoresT[(size_t)BB * FG * NN];   // thresholded fg scores [B][80][N]
__device__ float4 g_boxes4[(size_t)BB * NN];         // decoded boxes
__device__ float  g_cls_sc[(size_t)BB * FG * KPRE];  // per-class NMS'd scores
__device__ float4 g_cls_bx4[(size_t)BB * FG * KPRE]; // per-class top-200 boxes
__device__ unsigned g_bm[(size_t)BB * FG * BMW];     // candidate bitmaps (7.9 MB)

__device__ __forceinline__ ull make_key(unsigned bits, unsigned i)
{
    return ((ull)bits << 32) | (ull)(~i);
}

// ---------------------------------------------------------------------------
// Kernel 0: zero the candidate bitmaps (required per graph replay).
// ---------------------------------------------------------------------------
__global__ void __launch_bounds__(1024) k_zero()
{
    int i = blockIdx.x * 1024 + threadIdx.x;
    if (i < BB * FG * BMW) g_bm[i] = 0u;
}

// ---------------------------------------------------------------------------
// Kernel 1: warp-per-anchor softmax in XLA-GPU reduction order (bit-exact,
// validated R5-R11), threshold, transpose-store; box decode; bitmap RED.OR
// (fire-and-forget, no return dependency) for scores >= 0.0625.
// ---------------------------------------------------------------------------
__global__ void __launch_bounds__(1024) k_prep(const float* __restrict__ logits,
                                               const float* __restrict__ bbox,
                                               const float* __restrict__ priors)
{
    __shared__ float    tile[FG * 33];
    __shared__ unsigned basev[32];

    int tid  = threadIdx.x;
    int w    = tid >> 5;
    int lane = tid & 31;

    int a = blockIdx.x * 32 + w;
    int b = a / NN;
    int n = a - b * NN;

    const float* row = logits + (size_t)a * CC;

    float x0 = row[lane];
    float x1 = row[lane + 32];
    bool  h2 = (lane + 64) < CC;
    float x2 = h2 ? row[lane + 64] : -__int_as_float(0x7f800000);
    float m = fmaxf(fmaxf(x0, x1), x2);
#pragma unroll
    for (int off = 16; off > 0; off >>= 1)
        m = fmaxf(m, __shfl_xor_sync(0xFFFFFFFFu, m, off));

    float e0 = expf(__fsub_rn(x0, m));
    float e1 = expf(__fsub_rn(x1, m));
    float e2 = h2 ? expf(__fsub_rn(x2, m)) : 0.f;

    float acc = __fadd_rn(__fadd_rn(e0, e1), h2 ? e2 : 0.f);
    if (!h2) acc = __fadd_rn(e0, e1);
#pragma unroll
    for (int off = 16; off > 0; off >>= 1)
        acc = __fadd_rn(acc, __shfl_down_sync(0xFFFFFFFFu, acc, off));
    float s = __shfl_sync(0xFFFFFFFFu, acc, 0);

    int bbase = b * FG;
    unsigned wword = (unsigned)(n >> 5);
    unsigned wbit  = 1u << (n & 31);

    if (lane >= 1) {
        float v = __fdiv_rn(e0, s);
        tile[(lane - 1) * 33 + w] = (v > 0.01f) ? v : 0.f;
        if (v >= 0.0625f)
            atomicOr(&g_bm[(size_t)(bbase + lane - 1) * BMW + wword], wbit);
    }
    {
        float v = __fdiv_rn(e1, s);
        tile[(lane + 31) * 33 + w] = (v > 0.01f) ? v : 0.f;
        if (v >= 0.0625f)
            atomicOr(&g_bm[(size_t)(bbase + lane + 31) * BMW + wword], wbit);
    }
    if (h2) {
        float v = __fdiv_rn(e2, s);
        tile[(lane + 63) * 33 + w] = (v > 0.01f) ? v : 0.f;
        if (v >= 0.0625f)
            atomicOr(&g_bm[(size_t)(bbase + lane + 63) * BMW + wword], wbit);
    }

    if (lane == 0) {
        basev[w] = (unsigned)(b * FG * NN + n);
        float4 p = ((const float4*)priors)[n];
        float4 t = ((const float4*)bbox)[a];
        float cx = __fadd_rn(__fmul_rn(__fmul_rn(t.x, 0.1f), p.z), p.x);
        float cy = __fadd_rn(__fmul_rn(__fmul_rn(t.y, 0.1f), p.w), p.y);
        float wd = __fmul_rn(expf(__fmul_rn(t.z, 0.2f)), p.z);
        float ht = __fmul_rn(expf(__fmul_rn(t.w, 0.2f)), p.w);
        float hw = __fmul_rn(wd, 0.5f);
        float hh = __fmul_rn(ht, 0.5f);
        float4 bx;
        bx.x = __fsub_rn(cx, hw);
        bx.y = __fsub_rn(cy, hh);
        bx.z = __fadd_rn(cx, hw);
        bx.w = __fadd_rn(cy, hh);
        g_boxes4[a] = bx;
    }
    __syncthreads();

#pragma unroll
    for (int i = tid; i < FG * 32; i += 1024) {
        int c = i >> 5;
        int j = i & 31;
        g_scoresT[(size_t)basev[j] + (size_t)c * NN] = tile[c * 33 + j];
    }
}

// ---------------------------------------------------------------------------
// Selection machinery (validated R7). Key ordering == jax.lax.top_k stable.
// ---------------------------------------------------------------------------
struct Sel {
    union {
        unsigned hist[NBIN];     // 8 KB (fallback path only)
        ull      keys[BUFCAP];   // 8 KB
    } u;
    unsigned chunk[NTH];
    unsigned vals[4];     // [0]=found [1]=bin [2]=above [3]=total
    unsigned counter;
};

// Warp-aggregated histogram add (all 32 lanes must execute; zero bits -> skip).
__device__ __forceinline__ void hist_add(unsigned* hist, unsigned bits, int lane,
                                         int shift)
{
    unsigned bin = bits ? (bits >> shift) : 0xFFFFFFFFu;
    unsigned peers = __match_any_sync(0xFFFFFFFFu, bin);
    int leader = __ffs(peers) - 1;
    if (lane == leader && bits) atomicAdd(&hist[bin], (unsigned)__popc(peers));
}

// Highest-first scan of hist[NBIN]: find bin where cumulative count (from top
// bin downward) first reaches K. Warp-parallel. Requires blockDim == NTH.
__device__ void find_cut(Sel* s, unsigned K)
{
    int tid = threadIdx.x;
    const int CPT = NBIN / NTH;               // 8 bins/thread
    unsigned cs = 0;
    int base = tid * CPT;
#pragma unroll
    for (int j = 0; j < CPT; j++) cs += s->u.hist[base + j];
    s->chunk[tid] = cs;
    __syncthreads();
    if (tid < 32) {
        unsigned ss = 0;
#pragma unroll
        for (int j = 0; j < 8; j++) ss += s->chunk[tid * 8 + j];
        unsigned incl = ss;                    // inclusive suffix sum (lane..31)
#pragma unroll
        for (int off = 1; off < 32; off <<= 1) {
            unsigned t = __shfl_down_sync(0xFFFFFFFFu, incl, off);
            if (tid + off < 32) incl += t;
        }
        unsigned total = __shfl_sync(0xFFFFFFFFu, incl, 0);
        unsigned above = incl - ss;            // strictly-higher lanes
        bool cross = (total >= K) && (above < K) && (incl >= K);
        if (tid == 0) { s->vals[0] = (total >= K) ? 1u : 0u; s->vals[3] = total; }
        if (cross) {
            unsigned acc = above; int bin = -1;
            for (int c = tid * 8 + 7; c >= tid * 8; c--) {
                unsigned cv = s->chunk[c];
                if (acc + cv >= K) {
                    for (int bq = c * CPT + CPT - 1; bq >= c * CPT; bq--) {
                        unsigned hv = s->u.hist[bq];
                        if (acc + hv >= K) { bin = bq; break; }
                        acc += hv;
                    }
                    break;
                }
                acc += cv;
            }
            s->vals[1] = (unsigned)bin;
            s->vals[2] = acc;
        }
    }
    __syncthreads();
}

__device__ void bitonic_desc(ull* keys, int L)
{
    for (int k = 2; k <= L; k <<= 1) {
        for (int j = k >> 1; j > 0; j >>= 1) {
            for (int i = threadIdx.x; i < L; i += NTH) {
                int ixj = i ^ j;
                if (ixj > i) {
                    ull a = keys[i], bkey = keys[ixj];
                    bool up = ((i & k) == 0);
                    if (up ? (a < bkey) : (a > bkey)) {
                        keys[i] = bkey; keys[ixj] = a;
                    }
                }
            }
            __syncthreads();
        }
    }
}

// Sort gathered keys (cnt entries) and emit top-K descending into outK.
__device__ void sort_emit(Sel* s, unsigned cnt, int K, ull* outK)
{
    int tid = threadIdx.x;
    if (cnt > BUFCAP) cnt = BUFCAP;
    int L = 1; while (L < (int)cnt) L <<= 1; if (L < 2) L = 2;
    for (int p = (int)cnt + tid; p < L; p += NTH) s->u.keys[p] = 0ull;
    __syncthreads();
    bitonic_desc(s->u.keys, L);
    for (int j = tid; j < K; j += NTH) outK[j] = s->u.keys[j];
    __syncthreads();
}

// Deficit path (fewer than K positives): gather all, sort, fill stable zeros.
__device__ void deficit_path(const float4* __restrict__ row4, int n, int K,
                             unsigned total, Sel* s, ull* outK)
{
    int tid = threadIdx.x;
    int n4 = n >> 2;
    if (tid == 0) s->counter = 0;
    __syncthreads();
    for (int i = tid; i < n4; i += NTH) {
        float4 v = row4[i];
        unsigned bb[4] = { __float_as_uint(v.x), __float_as_uint(v.y),
                           __float_as_uint(v.z), __float_as_uint(v.w) };
#pragma unroll
        for (int c = 0; c < 4; c++)
            if (bb[c]) {
                unsigned p = atomicAdd(&s->counter, 1u);
                if (p < BUFCAP) s->u.keys[p] = make_key(bb[c], (unsigned)(i * 4 + c));
            }
    }
    __syncthreads();
    int L = 1; while (L < (int)total) L <<= 1; if (L < 2) L = 2;
    for (int p = (int)total + tid; p < L; p += NTH) s->u.keys[p] = 0ull;
    __syncthreads();
    bitonic_desc(s->u.keys, L);
    for (int j = tid; j < (int)total && j < K; j += NTH) outK[j] = s->u.keys[j];
    __syncthreads();
    if (tid == 0) {
        const float* rowf = (const float*)row4;
        int filled = (int)total;
        for (int i = 0; filled < K && i < n; i++)
            if (__float_as_uint(rowf[i]) == 0u)
                outK[filled++] = make_key(0u, (unsigned)i);
    }
    __syncthreads();
}

// Full in-block stable top-K (fallback + k_final; validated R7 path).
__device__ void stable_topk(const float4* __restrict__ row4, int n, int K,
                            Sel* s, ull* outK)
{
    int tid = threadIdx.x;
    int lane = tid & 31;
    int n4 = n >> 2;
    int iters = (n4 + NTH - 1) / NTH;

    for (int i = tid; i < NBIN; i += NTH) s->u.hist[i] = 0;
    __syncthreads();

    for (int it = 0; it < iters; it++) {
        int i = it * NTH + tid;
        bool in = (i < n4);
        float4 v = in ? row4[i] : make_float4(0.f, 0.f, 0.f, 0.f);
        hist_add(s->u.hist, __float_as_uint(v.x), lane, 19);
        hist_add(s->u.hist, __float_as_uint(v.y), lane, 19);
        hist_add(s->u.hist, __float_as_uint(v.z), lane, 19);
        hist_add(s->u.hist, __float_as_uint(v.w), lane, 19);
    }
    __syncthreads();
    find_cut(s, (unsigned)K);

    if (s->vals[0]) {
        unsigned bin   = s->vals[1];
        unsigned above = s->vals[2];
        unsigned inbin = s->u.hist[bin];
        unsigned pivot = bin << 19;
        __syncthreads();    // all hist reads done before keys (union) is written

        if (above + inbin > BUFCAP) {
            for (int i = tid; i < NBIN; i += NTH) s->u.hist[i] = 0;
            __syncthreads();
            for (int it = 0; it < iters; it++) {
                int i = it * NTH + tid;
                bool in = (i < n4);
                float4 v = in ? row4[i] : make_float4(0.f, 0.f, 0.f, 0.f);
                unsigned bb[4] = { __float_as_uint(v.x), __float_as_uint(v.y),
                                   __float_as_uint(v.z), __float_as_uint(v.w) };
#pragma unroll
                for (int c = 0; c < 4; c++) {
                    bool sel = bb[c] && ((bb[c] >> 19) == bin);
                    if (sel) atomicAdd(&s->u.hist[(bb[c] >> 8) & 0x7FFu], 1u);
                }
            }
            __syncthreads();
            find_cut(s, (unsigned)K - above);
            pivot = (bin << 19) | (s->vals[1] << 8);
            __syncthreads();
        }

        if (tid == 0) s->counter = 0;
        __syncthreads();
        for (int i = tid; i < n4; i += NTH) {
            float4 v = row4[i];
            unsigned bb[4] = { __float_as_uint(v.x), __float_as_uint(v.y),
                               __float_as_uint(v.z), __float_as_uint(v.w) };
#pragma unroll
            for (int c = 0; c < 4; c++) {
                if (bb[c] && bb[c] >= pivot) {
                    unsigned p = atomicAdd(&s->counter, 1u);
                    if (p < BUFCAP) s->u.keys[p] = make_key(bb[c], (unsigned)(i * 4 + c));
                }
            }
        }
        __syncthreads();
        sort_emit(s, s->counter, K, outK);
    } else {
        unsigned total = s->vals[3];
        __syncthreads();
        deficit_path(row4, n, K, total, s, outK);
    }
}

// ---------------------------------------------------------------------------
// Kernel 2: per-(batch,class) top-200 from candidate bitmap (16 KB read vs
// 98 KB row stream; fallback: full stable_topk), then bitmap greedy NMS.
// ---------------------------------------------------------------------------
#define NW 7   // ceil(KPRE/32)

struct K2Smem {
    Sel      sel;
    ull      outK[KPRE];
    float4   bxs[KPRE];
    float    scs[KPRE];
    float    area[KPRE];
    unsigned iou_w[KPRE][NW];
    unsigned keepw[NW];
    unsigned cnt_total;
    unsigned append_base;
};

__global__ void __launch_bounds__(NTH, 8) k_nms()
{
    __shared__ K2Smem s;
    int bc = blockIdx.x;            // b*80 + c
    int b  = bc / FG;
    int j  = threadIdx.x;
    int lane = j & 31;

    const float*  rowf = g_scoresT + (size_t)bc * NN;
    const float4* row4 = (const float4*)rowf;

    // ---- Load bitmap (3 coalesced words/thread) and count set bits ----
    if (j == 0) { s.cnt_total = 0; s.append_base = 0; }
    __syncthreads();
    unsigned myw[3]; unsigned mycnt = 0;
    const unsigned* bmrow = g_bm + (size_t)bc * BMW;
#pragma unroll
    for (int q = 0; q < 3; q++) {
        myw[q] = bmrow[j + q * NTH];
        mycnt += (unsigned)__popc(myw[q]);
    }
    {
        unsigned wsum = mycnt;
#pragma unroll
        for (int off = 16; off > 0; off >>= 1)
            wsum += __shfl_down_sync(0xFFFFFFFFu, wsum, off);
        if (lane == 0 && wsum) atomicAdd(&s.cnt_total, wsum);
    }
    __syncthreads();
    unsigned cnt = s.cnt_total;

    if (cnt >= (unsigned)KPRE && cnt <= BUFCAP) {
        // ---- Fast path: append keys for set bits (warp scan + 1 atomic/warp).
        // Bitmap == {n : score >= 0.0625} exactly (set by k_prep); every
        // top-KPRE key satisfies this whenever cnt >= KPRE, and cnt <= BUFCAP
        // guarantees no drops. Sort canonicalizes order.
        unsigned incl = mycnt;
#pragma unroll
        for (int off = 1; off < 32; off <<= 1) {
            unsigned t = __shfl_up_sync(0xFFFFFFFFu, incl, off);
            if (lane >= off) incl += t;
        }
        unsigned excl = incl - mycnt;
        unsigned wtot = __shfl_sync(0xFFFFFFFFu, incl, 31);
        unsigned base = 0;
        if (lane == 31 && wtot) base = atomicAdd(&s.append_base, wtot);
        base = __shfl_sync(0xFFFFFFFFu, base, 31);
        unsigned pos = base + excl;
#pragma unroll
        for (int q = 0; q < 3; q++) {
            unsigned wv = myw[q];
            unsigned wbase = (unsigned)(j + q * NTH) * 32u;
            while (wv) {
                int t = __ffs(wv) - 1;
                wv &= wv - 1;
                unsigned n = wbase + (unsigned)t;
                unsigned bits = __float_as_uint(rowf[n]);
                s.sel.u.keys[pos++] = make_key(bits, n);
            }
        }
        __syncthreads();
        sort_emit(&s.sel, cnt, KPRE, s.outK);
    } else {
        stable_topk(row4, NN, KPRE, &s.sel, s.outK);   // exact fallback (rare)
    }

    if (j < KPRE) {
        ull key = s.outK[j];
        unsigned bits = (unsigned)(key >> 32);
        unsigned idx  = ~(unsigned)(key & 0xFFFFFFFFull);
        float4 bx = g_boxes4[(size_t)b * NN + idx];
        s.scs[j]  = __uint_as_float(bits);
        s.bxs[j]  = bx;
        s.area[j] = __fmul_rn(fmaxf(__fsub_rn(bx.z, bx.x), 0.f),
                              fmaxf(__fsub_rn(bx.w, bx.y), 0.f));
    }
    for (int t = j; t < KPRE * NW; t += NTH) s.iou_w[0][t] = 0u;
    __syncthreads();

    // ---- Triangle IoU (i<=j) with mirror atomicOr into bitmap ----
    for (int t = j; t < NPAIRS; t += NTH) {
        int i = (int)(200.5f - 0.5f * sqrtf(160801.0f - 8.0f * (float)t));
        if (i > KPRE - 1) i = KPRE - 1;
        if (i < 0) i = 0;
        while ((i + 1) * (2 * KPRE - 1 - i + 1) / 2 <= t) i++;
        while (i * (2 * KPRE + 1 - i) / 2 > t) i--;
        int jj = i + (t - i * (2 * KPRE + 1 - i) / 2);

        float4 a = s.bxs[i], bx = s.bxs[jj];
        float lx = fmaxf(a.x, bx.x), ly = fmaxf(a.y, bx.y);
        float rx = fminf(a.z, bx.z), ry = fminf(a.w, bx.w);
        float iw = fmaxf(__fsub_rn(rx, lx), 0.f), ih = fmaxf(__fsub_rn(ry, ly), 0.f);
        float inter = __fmul_rn(iw, ih);
        float uni = __fsub_rn(__fadd_rn(s.area[i], s.area[jj]), inter);
        float iou = __fdiv_rn(inter, fmaxf(uni, 1e-9f));
        if (iou > 0.45f) {
            atomicOr(&s.iou_w[i][jj >> 5], 1u << (jj & 31));
            if (i != jj) atomicOr(&s.iou_w[jj][i >> 5], 1u << (i & 31));
        }
    }
    __syncthreads();

    // ---- Greedy scan (reference lax.scan semantics), single thread ----
    if (j == 0) {
        unsigned sp0 = 0, sp1 = 0, sp2 = 0, sp3 = 0, sp4 = 0, sp5 = 0, sp6 = 0;
#define NMS_WORD(W, SUPPW)                                              \
        {                                                               \
            int lim = KPRE - (W) * 32; if (lim > 32) lim = 32;          \
            unsigned kw = 0;                                            \
            for (int bi = 0; bi < lim; bi++) {                          \
                int i = (W) * 32 + bi;                                  \
                unsigned r0 = s.iou_w[i][0], r1 = s.iou_w[i][1],        \
                         r2 = s.iou_w[i][2], r3 = s.iou_w[i][3],        \
                         r4 = s.iou_w[i][4], r5 = s.iou_w[i][5],        \
                         r6 = s.iou_w[i][6];                            \
                bool ki = (s.scs[i] > 0.f) && !((SUPPW >> bi) & 1u);    \
                if (ki) {                                               \
                    kw |= 1u << bi;                                     \
                    sp0 |= r0; sp1 |= r1; sp2 |= r2; sp3 |= r3;         \
                    sp4 |= r4; sp5 |= r5; sp6 |= r6;                    \
                }                                                       \
            }                                                           \
            s.keepw[W] = kw;                                            \
        }
        NMS_WORD(0, sp0) NMS_WORD(1, sp1) NMS_WORD(2, sp2) NMS_WORD(3, sp3)
        NMS_WORD(4, sp4) NMS_WORD(5, sp5) NMS_WORD(6, sp6)
#undef NMS_WORD
    }
    __syncthreads();

    if (j < KPRE) {
        bool kept = (s.keepw[j >> 5] >> (j & 31)) & 1u;
        size_t o = (size_t)bc * KPRE + j;
        g_cls_sc[o]  = kept ? s.scs[j] : 0.0f;
        g_cls_bx4[o] = s.bxs[j];
    }
}

// ---------------------------------------------------------------------------
// Kernel 3: per-batch stable top-100 over 16000 class-scores; write outputs.
// ---------------------------------------------------------------------------
struct K3Smem {
    Sel sel;
    ull outK[KDET];
};

__global__ void __launch_bounds__(NTH) k_final(float* __restrict__ out)
{
    __shared__ K3Smem s;
    int b = blockIdx.x;
    int j = threadIdx.x;
    const int FLAT = FG * KPRE;     // 16000

    const float4* row4 = (const float4*)(g_cls_sc + (size_t)b * FLAT);
    stable_topk(row4, FLAT, KDET, &s.sel, s.outK);

    if (j < KDET) {
        ull key = s.outK[j];
        unsigned bits = (unsigned)(key >> 32);
        unsigned f    = ~(unsigned)(key & 0xFFFFFFFFull);
        float4 bx = g_cls_bx4[(size_t)b * FLAT + f];
        float* obx = out + ((size_t)b * KDET + j) * 4;
        obx[0] = bx.x; obx[1] = bx.y; obx[2] = bx.z; obx[3] = bx.w;
        out[BB * KDET * 4 + b * KDET + j]             = __uint_as_float(bits);
        out[BB * KDET * 4 + BB * KDET + b * KDET + j] = (float)(f / KPRE + 1);
    }
}

// ---------------------------------------------------------------------------
extern "C" void kernel_launch(void* const* d_in, const int* in_sizes, int n_in,
                              void* d_out, int out_size)
{
    const float* logits = (const float*)d_in[0];
    const float* bbox   = (const float*)d_in[1];
    const float* priors = (const float*)d_in[2];
    float* out = (float*)d_out;

    k_zero<<<(BB * FG * BMW + 1023) / 1024, 1024>>>();
    k_prep<<<(BB * NN) / 32, 1024>>>(logits, bbox, priors);
    k_nms<<<BB * FG, NTH>>>();
    k_final<<<BB, NTH>>>(out);
}